// round 9
// baseline (speedup 1.0000x reference)
#include <cuda_runtime.h>
#include <cuda_bf16.h>

// BCELoss(reduce=False) with "correct-side" masking.
//   y in {0,1}. q = y ? p : 1-p.  loss = (q > 0.5) ? 0 : -max(log q, -100)
// log(1-p) only evaluated when p >= 0.5 -> 1-p exact (Sterbenz), matches
// reference log1p(-p) to fp32 precision. Single MUFU.LG2 per element.
//
// FINAL (R8 = best measured config, from R4):
//   - contiguous flat partition: each 512-thread CTA owns 1024 consecutive
//     float4 slots (16 KB per stream) -> best DRAM sector locality
//     (strided-persistent variant measured 4% worse DRAM%)
//   - 2 float4 slots/thread, 4 front-batched LDG.128 (MLP=4; MLP=8 neutral)
//   - default cache ops (.ca/.wb): ldcs/stcs regressed, ldcg neutral
// Measured: 26.75us kernel, DRAM 77.8%, 6157 GB/s — the hardware wall for
// this 128MB-read/64MB-write fp32 stream (confirmed across MLP 2/4/8,
// block 256/512, grid 608..16384, all cache-op variants: all 26.6-26.8us).

__device__ __forceinline__ float bce_elem(float p, float y) {
    float q = (y > 0.5f) ? p : (1.0f - p);
    if (q > 0.5f) return 0.0f;
    return -fmaxf(__logf(q), -100.0f);
}

__device__ __forceinline__ float4 bce_vec4(float4 p, float4 y) {
    float4 o;
    o.x = bce_elem(p.x, y.x);
    o.y = bce_elem(p.y, y.y);
    o.z = bce_elem(p.z, y.z);
    o.w = bce_elem(p.w, y.w);
    return o;
}

__global__ void __launch_bounds__(512)
neo_loss_vec8(const float4* __restrict__ pred,
              const float4* __restrict__ actual,
              float4* __restrict__ out,
              int n4) {
    // each thread handles 2 float4 slots: base and base+512 (coalesced)
    int base = blockIdx.x * 1024 + threadIdx.x;
    int i1 = base + 512;

    if (i1 < n4) {
        // front-batch all 4 loads -> 4 outstanding LDG.128 per thread
        float4 p0 = pred[base];
        float4 p1 = pred[i1];
        float4 y0 = actual[base];
        float4 y1 = actual[i1];
        out[base] = bce_vec4(p0, y0);
        out[i1]   = bce_vec4(p1, y1);
    } else if (base < n4) {
        float4 p0 = pred[base];
        float4 y0 = actual[base];
        out[base] = bce_vec4(p0, y0);
    }
}

__global__ void neo_loss_tail(const float* __restrict__ pred,
                              const float* __restrict__ actual,
                              float* __restrict__ out,
                              int start, int n) {
    int i = start + blockIdx.x * blockDim.x + threadIdx.x;
    if (i >= n) return;
    out[i] = bce_elem(pred[i], actual[i]);
}

extern "C" void kernel_launch(void* const* d_in, const int* in_sizes, int n_in,
                              void* d_out, int out_size) {
    const float* pred   = (const float*)d_in[0];
    const float* actual = (const float*)d_in[1];
    float* out = (float*)d_out;
    int n = in_sizes[0];

    int n4 = n >> 2;            // float4 count
    int vec_elems = n4 << 2;

    if (n4 > 0) {
        // 1024 float4 slots per block (2 per thread, 512 threads)
        int blocks = (n4 + 1023) / 1024;
        neo_loss_vec8<<<blocks, 512>>>(
            (const float4*)pred, (const float4*)actual, (float4*)out, n4);
    }
    if (vec_elems < n) {
        int rem = n - vec_elems;
        neo_loss_tail<<<(rem + 255) / 256, 256>>>(pred, actual, out, vec_elems, n);
    }
}

// round 10
// speedup vs baseline: 1.0214x; 1.0214x over previous
#include <cuda_runtime.h>
#include <cuda_bf16.h>

// BCELoss(reduce=False) with "correct-side" masking.
//   y in {0,1}. q = y ? p : 1-p.  loss = (q > 0.5) ? 0 : -max(log q, -100)
// log(1-p) only evaluated when p >= 0.5 -> 1-p exact (Sterbenz), matches
// reference log1p(-p) to fp32 precision. Single MUFU.LG2 per element.
//
// R9: R4's best-measured geometry (contiguous 1024-slot/CTA partition,
// 512 threads, 2 float4 slots/thread, 4 front-batched LDG.128, default
// cache ops) with the bounds predicates REMOVED from the hot path: the
// exactly-divisible prefix runs an unguarded kernel; a guarded remainder
// kernel covers leftovers (never launched for N=2^24).
// Measured wall across 7 configs: 26.6-26.8us kernel, ~6.15 TB/s —
// DRAM-limited; all SM pipes <18%.

__device__ __forceinline__ float bce_elem(float p, float y) {
    float q = (y > 0.5f) ? p : (1.0f - p);
    if (q > 0.5f) return 0.0f;
    return -fmaxf(__logf(q), -100.0f);
}

__device__ __forceinline__ float4 bce_vec4(float4 p, float4 y) {
    float4 o;
    o.x = bce_elem(p.x, y.x);
    o.y = bce_elem(p.y, y.y);
    o.z = bce_elem(p.z, y.z);
    o.w = bce_elem(p.w, y.w);
    return o;
}

// Full blocks only: no bounds checks, straight-line code.
__global__ void __launch_bounds__(512)
neo_loss_full(const float4* __restrict__ pred,
              const float4* __restrict__ actual,
              float4* __restrict__ out) {
    int base = blockIdx.x * 1024 + threadIdx.x;
    int i1 = base + 512;
    // 4 front-batched LDG.128 per thread
    float4 p0 = pred[base];
    float4 p1 = pred[i1];
    float4 y0 = actual[base];
    float4 y1 = actual[i1];
    out[base] = bce_vec4(p0, y0);
    out[i1]   = bce_vec4(p1, y1);
}

// Guarded remainder over scalar elements [start, n).
__global__ void neo_loss_rem(const float* __restrict__ pred,
                             const float* __restrict__ actual,
                             float* __restrict__ out,
                             int start, int n) {
    int i = start + blockIdx.x * blockDim.x + threadIdx.x;
    if (i >= n) return;
    out[i] = bce_elem(pred[i], actual[i]);
}

extern "C" void kernel_launch(void* const* d_in, const int* in_sizes, int n_in,
                              void* d_out, int out_size) {
    const float* pred   = (const float*)d_in[0];
    const float* actual = (const float*)d_in[1];
    float* out = (float*)d_out;
    int n = in_sizes[0];

    int n4 = n >> 2;                    // float4 count
    int full_blocks = n4 >> 10;         // 1024 float4 slots per block
    int covered = (full_blocks << 10) << 2;  // elements covered unguarded

    if (full_blocks > 0) {
        neo_loss_full<<<full_blocks, 512>>>(
            (const float4*)pred, (const float4*)actual, (float4*)out);
    }
    if (covered < n) {
        int rem = n - covered;
        neo_loss_rem<<<(rem + 255) / 256, 256>>>(pred, actual, out, covered, n);
    }
}